// round 1
// baseline (speedup 1.0000x reference)
#include <cuda_runtime.h>
#include <cuda_bf16.h>

// Problem constants
#define BATCH 16
#define T_STEPS 128
#define N_STATE 256
#define D_T 64
#define D_IN 64
#define NUM_BT (BATCH * T_STEPS)        // 2048
#define NUM_LEAF (N_STATE * 64)         // 16384
#define K_DIM 384                       // 256 + 64 + 64

// Scratch (static device allocations are allowed)
__device__ float gA[NUM_BT * K_DIM];          // concatenated input rows [2048][384]
__device__ float gT3[T_STEPS * 4096];         // tproj3 [t][4096]
__device__ float gT2[T_STEPS * 1024];         // tproj2 [t][1024]
__device__ float gT1[T_STEPS * 256];          // tproj1 [t][256]

__device__ __forceinline__ float softplus_f(float x) {
    // matches jax.nn.softplus: max(x,0) + log1p(exp(-|x|))
    return fmaxf(x, 0.0f) + log1pf(expf(-fabsf(x)));
}

// ---------------------------------------------------------------------------
// Kernel 1: build A_cat[bt][k] = concat(x[bt], t_emb[t], input_vector[bt])
// ---------------------------------------------------------------------------
__global__ void prep_kernel(const float* __restrict__ x,
                            const float* __restrict__ temb,
                            const float* __restrict__ iv) {
    int idx = blockIdx.x * blockDim.x + threadIdx.x;
    if (idx >= NUM_BT * K_DIM) return;
    int bt = idx / K_DIM;
    int k = idx - bt * K_DIM;
    float v;
    if (k < 256)       v = x[bt * 256 + k];
    else if (k < 320)  v = temb[(bt & (T_STEPS - 1)) * 64 + (k - 256)];
    else               v = iv[bt * 64 + (k - 320)];
    gA[idx] = v;
}

// ---------------------------------------------------------------------------
// Kernel 2: tproj3/2/1 = t_emb @ tW.T + tb
// One thread owns one weight row (64 floats in registers), loops all 128 t
// with t_emb resident in shared -> each tW matrix read exactly once.
// ---------------------------------------------------------------------------
__global__ void tproj_kernel(const float* __restrict__ temb,
                             const float* __restrict__ tW3, const float* __restrict__ tb3,
                             const float* __restrict__ tW2, const float* __restrict__ tb2,
                             const float* __restrict__ tW1, const float* __restrict__ tb1) {
    __shared__ float te[T_STEPS * 64];
    int tid = threadIdx.x;
    for (int i = tid; i < T_STEPS * 64; i += 256) te[i] = temb[i];
    __syncthreads();

    int j = blockIdx.x * 256 + tid;    // 0 .. 5375
    if (j >= 4096 + 1024 + 256) return;

    const float* Wrow;
    float bias;
    float* outp;
    int stride;
    if (j < 4096)      { Wrow = tW3 + j * 64;            bias = tb3[j];        outp = gT3 + j;          stride = 4096; }
    else if (j < 5120) { int q = j - 4096; Wrow = tW2 + q * 64; bias = tb2[q]; outp = gT2 + q;          stride = 1024; }
    else               { int q = j - 5120; Wrow = tW1 + q * 64; bias = tb1[q]; outp = gT1 + q;          stride = 256;  }

    float w[64];
#pragma unroll
    for (int m = 0; m < 64; m++) w[m] = Wrow[m];

    for (int t = 0; t < T_STEPS; t++) {
        float s = bias;
        const float* tev = &te[t * 64];
#pragma unroll
        for (int m = 0; m < 64; m++) s = fmaf(w[m], tev[m], s);
        outp[t * stride] = s;
    }
}

// ---------------------------------------------------------------------------
// Kernel 3: fused GEMM (pre = A @ Wcat^T + ba) + softplus dendritic tree.
// Tile: 64 bt-rows x 128 leaves, K-chunks of 8. 256 threads, 4x8 microtile.
// Epilogue: leaf->g (x w3, sum4, +tproj3), g->h (x w2), h->n (x w1).
// ---------------------------------------------------------------------------
__global__ __launch_bounds__(256) void main_kernel(
        const float* __restrict__ Wa, const float* __restrict__ Wt,
        const float* __restrict__ Wi, const float* __restrict__ ba,
        const float* __restrict__ w3, const float* __restrict__ w2,
        const float* __restrict__ w1, float* __restrict__ out) {

    __shared__ float As[8][68];     // padded: conflict-free transposed store
    __shared__ float Bs[8][132];    // padded
    __shared__ float epi[64][33];   // act2 per (bt, local g)   (32 g per block)
    __shared__ float epi2[64][9];   // act1 per (bt, local h)   (8 h per block)

    const int tid = threadIdx.x;
    const int tx = tid & 15;        // 0..15 -> leaf cols tx*8..+7
    const int ty = tid >> 4;        // 0..15 -> bt rows  ty*4..+3
    const int bt0 = blockIdx.y * 64;
    const int leaf0 = blockIdx.x * 128;

    float acc[4][8];
#pragma unroll
    for (int i = 0; i < 4; i++)
#pragma unroll
        for (int j = 0; j < 8; j++) acc[i][j] = 0.0f;

    for (int k0 = 0; k0 < K_DIM; k0 += 8) {
        __syncthreads();
        // --- load A tile [64 bt x 8 k], transposed into As[k][bt]
        {
            int e = tid;
            int row = e >> 3, kk = e & 7;
            As[kk][row] = gA[(bt0 + row) * K_DIM + k0 + kk];
            e = tid + 256;
            row = e >> 3; kk = e & 7;
            As[kk][row] = gA[(bt0 + row) * K_DIM + k0 + kk];
        }
        // --- load B tile [8 k x 128 leaf] from Wa/Wt/Wi (k-chunk never straddles)
        {
            int ll = tid >> 1;
            int kk4 = (tid & 1) * 4;
            int kg = k0 + kk4;
            const float* p;
            if (k0 < 256)      p = Wa + (leaf0 + ll) * 256 + kg;
            else if (k0 < 320) p = Wt + (leaf0 + ll) * 64 + (kg - 256);
            else               p = Wi + (leaf0 + ll) * 64 + (kg - 320);
            float4 v = *(const float4*)p;
            Bs[kk4 + 0][ll] = v.x;
            Bs[kk4 + 1][ll] = v.y;
            Bs[kk4 + 2][ll] = v.z;
            Bs[kk4 + 3][ll] = v.w;
        }
        __syncthreads();
#pragma unroll
        for (int kk = 0; kk < 8; kk++) {
            float4 a  = *(const float4*)&As[kk][ty * 4];
            float4 b0 = *(const float4*)&Bs[kk][tx * 8];
            float4 b1 = *(const float4*)&Bs[kk][tx * 8 + 4];
            float av[4] = {a.x, a.y, a.z, a.w};
            float bv[8] = {b0.x, b0.y, b0.z, b0.w, b1.x, b1.y, b1.z, b1.w};
#pragma unroll
            for (int i = 0; i < 4; i++)
#pragma unroll
                for (int j = 0; j < 8; j++)
                    acc[i][j] = fmaf(av[i], bv[j], acc[i][j]);
        }
    }

    // ------------------- epilogue: dendritic tree -------------------
    const int lb = leaf0 + tx * 8;          // this thread's 8 consecutive leaves
    float ba_l[8], w3_l[8];
#pragma unroll
    for (int j = 0; j < 8; j++) { ba_l[j] = ba[lb + j]; w3_l[j] = w3[lb + j]; }

#pragma unroll
    for (int i = 0; i < 4; i++) {
        int btl = ty * 4 + i;
        int bt = bt0 + btl;
        int t = bt & (T_STEPS - 1);
        float s0 = 0.0f, s1 = 0.0f;
#pragma unroll
        for (int j = 0; j < 8; j++) {
            float a3 = softplus_f(acc[i][j] + ba_l[j]);
            float m = w3_l[j] * a3;
            if (j < 4) s0 += m; else s1 += m;
        }
        int g0 = lb >> 2;                    // global g index (leaf/4)
        float p30 = s0 + gT3[t * 4096 + g0];
        float p31 = s1 + gT3[t * 4096 + g0 + 1];
        epi[btl][tx * 2]     = softplus_f(p30);
        epi[btl][tx * 2 + 1] = softplus_f(p31);
    }
    __syncthreads();

    // level 2: 64 bt x 8 h  (h = g/4); g_global = blockIdx.x*32 + local
#pragma unroll
    for (int rep = 0; rep < 2; rep++) {
        int idx = tid + rep * 256;
        int btl = idx >> 3, hl = idx & 7;
        int bt = bt0 + btl;
        int t = bt & (T_STEPS - 1);
        int gg = blockIdx.x * 32 + hl * 4;
        float s = 0.0f;
#pragma unroll
        for (int b = 0; b < 4; b++)
            s = fmaf(w2[gg + b], epi[btl][hl * 4 + b], s);
        float p2 = s + gT2[t * 1024 + blockIdx.x * 8 + hl];
        epi2[btl][hl] = softplus_f(p2);
    }
    __syncthreads();

    // level 1: 64 bt x 2 n -> output
    if (tid < 128) {
        int btl = tid >> 1, nl = tid & 1;
        int bt = bt0 + btl;
        int t = bt & (T_STEPS - 1);
        int n = blockIdx.x * 2 + nl;
        float s = 0.0f;
#pragma unroll
        for (int a = 0; a < 4; a++)
            s = fmaf(w1[n * 4 + a], epi2[btl][nl * 4 + a], s);
        float p1 = s + gT1[t * 256 + n];
        out[bt * 256 + n] = softplus_f(p1);
    }
}

// ---------------------------------------------------------------------------
extern "C" void kernel_launch(void* const* d_in, const int* in_sizes, int n_in,
                              void* d_out, int out_size) {
    const float* x    = (const float*)d_in[0];
    const float* temb = (const float*)d_in[1];
    const float* iv   = (const float*)d_in[2];
    const float* Wa   = (const float*)d_in[3];
    const float* ba   = (const float*)d_in[4];
    const float* Wt   = (const float*)d_in[5];
    const float* Wi   = (const float*)d_in[6];
    const float* w3   = (const float*)d_in[7];
    const float* tW3  = (const float*)d_in[8];
    const float* tb3  = (const float*)d_in[9];
    const float* w2   = (const float*)d_in[10];
    const float* tW2  = (const float*)d_in[11];
    const float* tb2  = (const float*)d_in[12];
    const float* w1   = (const float*)d_in[13];
    const float* tW1  = (const float*)d_in[14];
    const float* tb1  = (const float*)d_in[15];
    float* out = (float*)d_out;

    prep_kernel<<<(NUM_BT * K_DIM + 255) / 256, 256>>>(x, temb, iv);
    tproj_kernel<<<(4096 + 1024 + 256 + 255) / 256, 256>>>(temb, tW3, tb3, tW2, tb2, tW1, tb1);
    dim3 grid(NUM_LEAF / 128, NUM_BT / 64);
    main_kernel<<<grid, 256>>>(Wa, Wt, Wi, ba, w3, w2, w1, out);
}